// round 15
// baseline (speedup 1.0000x reference)
#include <cuda_runtime.h>
#include <cuda_fp16.h>

// SimpleRNN: 2-layer tanh RNN, B=8192, S=512, H=16, INPUT=1, fc on last step.
// R14: depth-1 MMA accumulation. All 12 mma.sync.m16n8k16 per substep write
// DISTINCT accumulators (hi/lo weight split and layer-1's two operand groups
// no longer serialize); merges are an FADD tree on the idle fma pipe. This
// cuts the cross-substep critical path from ~2*L_hmma to ~L_hmma. Everything
// else as R13: 16 batches/warp, registers-only recurrence, fp16 h, hi/lo
// exact weight split, lagged layer 1, MUFU tanh, 128 blocks x 4 warps.

#define SEQ     512
#define HID     16
#define WPB     4
#define THREADS (WPB * 32)
#define BATCH   8192

typedef unsigned int u32;

__device__ __forceinline__ float tanh_mufu(float v) {
    float r;
    asm("tanh.approx.f32 %0, %1;" : "=f"(r) : "f"(v));
    return r;
}
__device__ __forceinline__ u32 pack_h2(float a, float b) {
    __half2 h = __floats2half2_rn(a, b);
    return *reinterpret_cast<u32*>(&h);
}
__device__ __forceinline__ u32 pack_halves(__half a, __half b) {
    __half2 h = __halves2half2(a, b);
    return *reinterpret_cast<u32*>(&h);
}
// D += A @ B  (m16n8k16, f16 inputs, f32 accumulate)
__device__ __forceinline__ void mma16816(float& d0, float& d1, float& d2, float& d3,
                                         u32 a0, u32 a1, u32 a2, u32 a3,
                                         u32 b0, u32 b1) {
    asm("mma.sync.aligned.m16n8k16.row.col.f32.f16.f16.f32 "
        "{%0,%1,%2,%3}, {%4,%5,%6,%7}, {%8,%9}, {%0,%1,%2,%3};"
        : "+f"(d0), "+f"(d1), "+f"(d2), "+f"(d3)
        : "r"(a0), "r"(a1), "r"(a2), "r"(a3), "r"(b0), "r"(b1));
}

__global__ __launch_bounds__(THREADS)
void rnn2_kernel(const float* __restrict__ x,
                 const float* __restrict__ Wih0, const float* __restrict__ Whh0,
                 const float* __restrict__ bih0, const float* __restrict__ bhh0,
                 const float* __restrict__ Wih1, const float* __restrict__ Whh1,
                 const float* __restrict__ bih1, const float* __restrict__ bhh1,
                 const float* __restrict__ Wfc,  const float* __restrict__ bfc,
                 float* __restrict__ out)
{
    const int w    = threadIdx.x >> 5;
    const int lane = threadIdx.x & 31;
    const int g    = lane >> 2;      // group 0..7 (row / n index)
    const int tg   = lane & 3;       // thread-in-group (col pairs)
    const int base = (blockIdx.x * WPB + w) * 16;   // first batch of this warp

    // ---- B fragments: B[k][n] = W[n][k] (col-major k16n8), hi/lo split ----
    u32 Bh0[2][2], Bl0[2][2];   // Whh0
    u32 Bh1[2][2], Bl1[2][2];   // Wih1
    u32 Bh2[2][2], Bl2[2][2];   // Whh1
    {
        const float* Ws[3] = { Whh0, Wih1, Whh1 };
        for (int m = 0; m < 3; m++) {
            for (int tau = 0; tau < 2; tau++) {
                int n = g + 8 * tau;
                const float* row = Ws[m] + n * HID;
                float w0 = row[2 * tg],     w1 = row[2 * tg + 1];
                float w2 = row[2 * tg + 8], w3 = row[2 * tg + 9];
                __half h0 = __float2half_rn(w0), h1 = __float2half_rn(w1);
                __half h2 = __float2half_rn(w2), h3 = __float2half_rn(w3);
                __half l0 = __float2half_rn(w0 - __half2float(h0));
                __half l1 = __float2half_rn(w1 - __half2float(h1));
                __half l2 = __float2half_rn(w2 - __half2float(h2));
                __half l3 = __float2half_rn(w3 - __half2float(h3));
                u32 bh0 = pack_halves(h0, h1), bh1 = pack_halves(h2, h3);
                u32 bl0 = pack_halves(l0, l1), bl1 = pack_halves(l2, l3);
                if (m == 0) { Bh0[tau][0] = bh0; Bh0[tau][1] = bh1; Bl0[tau][0] = bl0; Bl0[tau][1] = bl1; }
                if (m == 1) { Bh1[tau][0] = bh0; Bh1[tau][1] = bh1; Bl1[tau][0] = bl0; Bl1[tau][1] = bl1; }
                if (m == 2) { Bh2[tau][0] = bh0; Bh2[tau][1] = bh1; Bl2[tau][0] = bl0; Bl2[tau][1] = bl1; }
            }
        }
    }

    // per-lane column constants, index j -> col {2tg, 2tg+1, 2tg+8, 2tg+9}
    float wi0c[4], c0c[4], c1c[4], wfcc[4];
    {
        int cols[4] = { 2 * tg, 2 * tg + 1, 2 * tg + 8, 2 * tg + 9 };
#pragma unroll
        for (int j = 0; j < 4; j++) {
            int c = cols[j];
            wi0c[j] = Wih0[c];
            c0c[j]  = bih0[c] + bhh0[c];
            c1c[j]  = bih1[c] + bhh1[c];
            wfcc[j] = Wfc[c];
        }
    }

    const float* xg_ptr  = x + (size_t)(base + g) * SEQ;
    const float* xg8_ptr = x + (size_t)(base + g + 8) * SEQ;

    // A fragments (fp16) for h0(t-1) and h1(t-2); start at zero state.
    u32 A0[4] = {0u, 0u, 0u, 0u};
    u32 A1[4] = {0u, 0u, 0u, 0u};

    // one substep at time t: consumes A0=h0(t-1), A1=h1(t-2) and x(t);
    // produces A0=h0(t), A1=h1(t-1). All 12 MMAs hit distinct accumulators.
    auto substep = [&](float xg, float xg8, bool zero_h1) {
        float e[8], el[8], f[8], f2[8], fl[8], fl2[8];
        // layer0 hi-acc init: wi0*x + bias (rows g / g+8 -> regs {0,1}/{2,3})
        e[0] = fmaf(wi0c[0], xg,  c0c[0]);
        e[1] = fmaf(wi0c[1], xg,  c0c[1]);
        e[2] = fmaf(wi0c[0], xg8, c0c[0]);
        e[3] = fmaf(wi0c[1], xg8, c0c[1]);
        e[4] = fmaf(wi0c[2], xg,  c0c[2]);
        e[5] = fmaf(wi0c[3], xg,  c0c[3]);
        e[6] = fmaf(wi0c[2], xg8, c0c[2]);
        e[7] = fmaf(wi0c[3], xg8, c0c[3]);
        // layer1 hi-acc init: bias only; all other accs zero
        f[0] = c1c[0]; f[1] = c1c[1]; f[2] = c1c[0]; f[3] = c1c[1];
        f[4] = c1c[2]; f[5] = c1c[3]; f[6] = c1c[2]; f[7] = c1c[3];
#pragma unroll
        for (int j = 0; j < 8; j++) { el[j] = 0.f; f2[j] = 0.f; fl[j] = 0.f; fl2[j] = 0.f; }

        // 12 independent MMAs (depth-1 chains)
        mma16816(e[0],  e[1],  e[2],  e[3],  A0[0], A0[1], A0[2], A0[3], Bh0[0][0], Bh0[0][1]);
        mma16816(e[4],  e[5],  e[6],  e[7],  A0[0], A0[1], A0[2], A0[3], Bh0[1][0], Bh0[1][1]);
        mma16816(el[0], el[1], el[2], el[3], A0[0], A0[1], A0[2], A0[3], Bl0[0][0], Bl0[0][1]);
        mma16816(el[4], el[5], el[6], el[7], A0[0], A0[1], A0[2], A0[3], Bl0[1][0], Bl0[1][1]);
        mma16816(f[0],  f[1],  f[2],  f[3],  A0[0], A0[1], A0[2], A0[3], Bh1[0][0], Bh1[0][1]);
        mma16816(f[4],  f[5],  f[6],  f[7],  A0[0], A0[1], A0[2], A0[3], Bh1[1][0], Bh1[1][1]);
        mma16816(fl[0], fl[1], fl[2], fl[3], A0[0], A0[1], A0[2], A0[3], Bl1[0][0], Bl1[0][1]);
        mma16816(fl[4], fl[5], fl[6], fl[7], A0[0], A0[1], A0[2], A0[3], Bl1[1][0], Bl1[1][1]);
        mma16816(f2[0], f2[1], f2[2], f2[3], A1[0], A1[1], A1[2], A1[3], Bh2[0][0], Bh2[0][1]);
        mma16816(f2[4], f2[5], f2[6], f2[7], A1[0], A1[1], A1[2], A1[3], Bh2[1][0], Bh2[1][1]);
        mma16816(fl2[0],fl2[1],fl2[2],fl2[3],A1[0], A1[1], A1[2], A1[3], Bl2[0][0], Bl2[0][1]);
        mma16816(fl2[4],fl2[5],fl2[6],fl2[7],A1[0], A1[1], A1[2], A1[3], Bl2[1][0], Bl2[1][1]);

        // merge (fma pipe) + tanh (MUFU) + repack: D layout == A layout per lane
        A0[0] = pack_h2(tanh_mufu(e[0] + el[0]), tanh_mufu(e[1] + el[1]));
        A0[1] = pack_h2(tanh_mufu(e[2] + el[2]), tanh_mufu(e[3] + el[3]));
        A0[2] = pack_h2(tanh_mufu(e[4] + el[4]), tanh_mufu(e[5] + el[5]));
        A0[3] = pack_h2(tanh_mufu(e[6] + el[6]), tanh_mufu(e[7] + el[7]));
        if (zero_h1) {
            A1[0] = A1[1] = A1[2] = A1[3] = 0u;   // h1(-1) = 0
        } else {
            float p0 = (f[0] + f2[0]) + (fl[0] + fl2[0]);
            float p1 = (f[1] + f2[1]) + (fl[1] + fl2[1]);
            float p2 = (f[2] + f2[2]) + (fl[2] + fl2[2]);
            float p3 = (f[3] + f2[3]) + (fl[3] + fl2[3]);
            float p4 = (f[4] + f2[4]) + (fl[4] + fl2[4]);
            float p5 = (f[5] + f2[5]) + (fl[5] + fl2[5]);
            float p6 = (f[6] + f2[6]) + (fl[6] + fl2[6]);
            float p7 = (f[7] + f2[7]) + (fl[7] + fl2[7]);
            A1[0] = pack_h2(tanh_mufu(p0), tanh_mufu(p1));
            A1[1] = pack_h2(tanh_mufu(p2), tanh_mufu(p3));
            A1[2] = pack_h2(tanh_mufu(p4), tanh_mufu(p5));
            A1[3] = pack_h2(tanh_mufu(p6), tanh_mufu(p7));
        }
    };

    float4 cg  = *(const float4*)xg_ptr;
    float4 cg8 = *(const float4*)xg8_ptr;

#pragma unroll 1
    for (int tc = 0; tc < SEQ; tc += 4) {
        int tn = (tc + 4 < SEQ) ? tc + 4 : (SEQ - 4);
        float4 ng  = *(const float4*)(xg_ptr + tn);
        float4 ng8 = *(const float4*)(xg8_ptr + tn);

        substep(cg.x, cg8.x, tc == 0);
        substep(cg.y, cg8.y, false);
        substep(cg.z, cg8.z, false);
        substep(cg.w, cg8.w, false);

        cg = ng; cg8 = ng8;
    }

    // ---- epilogue: h1(511) = tanh(Wih1 h0(511) + Whh1 h1(510) + c1) ----
    float f[8], f2[8], fl[8], fl2[8];
    f[0] = c1c[0]; f[1] = c1c[1]; f[2] = c1c[0]; f[3] = c1c[1];
    f[4] = c1c[2]; f[5] = c1c[3]; f[6] = c1c[2]; f[7] = c1c[3];
#pragma unroll
    for (int j = 0; j < 8; j++) { f2[j] = 0.f; fl[j] = 0.f; fl2[j] = 0.f; }
    mma16816(f[0],  f[1],  f[2],  f[3],  A0[0], A0[1], A0[2], A0[3], Bh1[0][0], Bh1[0][1]);
    mma16816(f[4],  f[5],  f[6],  f[7],  A0[0], A0[1], A0[2], A0[3], Bh1[1][0], Bh1[1][1]);
    mma16816(fl[0], fl[1], fl[2], fl[3], A0[0], A0[1], A0[2], A0[3], Bl1[0][0], Bl1[0][1]);
    mma16816(fl[4], fl[5], fl[6], fl[7], A0[0], A0[1], A0[2], A0[3], Bl1[1][0], Bl1[1][1]);
    mma16816(f2[0], f2[1], f2[2], f2[3], A1[0], A1[1], A1[2], A1[3], Bh2[0][0], Bh2[0][1]);
    mma16816(f2[4], f2[5], f2[6], f2[7], A1[0], A1[1], A1[2], A1[3], Bh2[1][0], Bh2[1][1]);
    mma16816(fl2[0],fl2[1],fl2[2],fl2[3],A1[0], A1[1], A1[2], A1[3], Bl2[0][0], Bl2[0][1]);
    mma16816(fl2[4],fl2[5],fl2[6],fl2[7],A1[0], A1[1], A1[2], A1[3], Bl2[1][0], Bl2[1][1]);

    float q0 = (f[0] + f2[0]) + (fl[0] + fl2[0]);
    float q1 = (f[1] + f2[1]) + (fl[1] + fl2[1]);
    float q2 = (f[2] + f2[2]) + (fl[2] + fl2[2]);
    float q3 = (f[3] + f2[3]) + (fl[3] + fl2[3]);
    float q4 = (f[4] + f2[4]) + (fl[4] + fl2[4]);
    float q5 = (f[5] + f2[5]) + (fl[5] + fl2[5]);
    float q6 = (f[6] + f2[6]) + (fl[6] + fl2[6]);
    float q7 = (f[7] + f2[7]) + (fl[7] + fl2[7]);

    // fc over n: row g uses regs {0,1} (cols 2tg,2tg+1) and tile1 {4,5};
    // row g+8 uses {2,3} and {6,7}.
    float pg  = wfcc[0] * tanh_mufu(q0) + wfcc[1] * tanh_mufu(q1)
              + wfcc[2] * tanh_mufu(q4) + wfcc[3] * tanh_mufu(q5);
    float pg8 = wfcc[0] * tanh_mufu(q2) + wfcc[1] * tanh_mufu(q3)
              + wfcc[2] * tanh_mufu(q6) + wfcc[3] * tanh_mufu(q7);
    pg  += __shfl_xor_sync(0xffffffffu, pg, 1, 4);
    pg8 += __shfl_xor_sync(0xffffffffu, pg8, 1, 4);
    pg  += __shfl_xor_sync(0xffffffffu, pg, 2, 4);
    pg8 += __shfl_xor_sync(0xffffffffu, pg8, 2, 4);
    if (tg == 0) {
        float b0 = bfc[0];
        out[base + g]     = pg + b0;
        out[base + g + 8] = pg8 + b0;
    }
}

extern "C" void kernel_launch(void* const* d_in, const int* in_sizes, int n_in,
                              void* d_out, int out_size)
{
    const float* x    = (const float*)d_in[0];
    const float* Wih0 = (const float*)d_in[1];
    const float* Whh0 = (const float*)d_in[2];
    const float* bih0 = (const float*)d_in[3];
    const float* bhh0 = (const float*)d_in[4];
    const float* Wih1 = (const float*)d_in[5];
    const float* Whh1 = (const float*)d_in[6];
    const float* bih1 = (const float*)d_in[7];
    const float* bhh1 = (const float*)d_in[8];
    const float* Wfc  = (const float*)d_in[9];
    const float* bfc  = (const float*)d_in[10];
    float* out = (float*)d_out;

    rnn2_kernel<<<BATCH / (WPB * 16), THREADS>>>(x, Wih0, Whh0, bih0, bhh0,
                                                 Wih1, Whh1, bih1, bhh1,
                                                 Wfc, bfc, out);
}